// round 15
// baseline (speedup 1.0000x reference)
#include <cuda_runtime.h>
#include <cuda_bf16.h>
#include <math.h>
#include <stdint.h>

#define BATCH 64
#define TT    2048
#define ENC   512
#define UNITS 512
#define VOCAB 32
#define TCH   16

// ---- device scratch (no allocations allowed) ----
__device__ float g_scoreP[BATCH * 2 * TT];
__device__ float g_ctx[BATCH * ENC];          // atomic-accumulated context
__device__ float g_gxP[8 * BATCH * 3 * UNITS];
__device__ float g_ghP[8 * BATCH * 3 * UNITS];
__device__ float g_hidP[16 * BATCH * UNITS];
__device__ float g_pcP[16 * BATCH * UNITS];
__device__ float g_pc[BATCH * UNITS];         // atomic-accumulated (init Wfab)
__device__ float g_fw[BATCH * UNITS];         // atomic-accumulated (init Wffb+Wfhb)
__device__ __align__(16) __nv_bfloat16 g_Hb[(size_t)BATCH * TT * ENC];  // bf16 H
__device__ __align__(16) __nv_bfloat16 g_W1Tb[UNITS * ENC];             // W1^T bf16 [n][k]

// =====================================================================
// helpers
// =====================================================================
__device__ __forceinline__ uint32_t smem_u32(const void* p) {
    uint32_t a;
    asm("{ .reg .u64 t; cvta.to.shared.u64 t, %1; cvt.u32.u64 %0, t; }"
        : "=r"(a) : "l"(p));
    return a;
}
#define CP16(dst, src) asm volatile( \
    "cp.async.cg.shared.global [%0], [%1], 16;\n" :: "r"(dst), "l"(src))
#define CP_COMMIT() asm volatile("cp.async.commit_group;\n")
#define CP_WAIT1()  asm volatile("cp.async.wait_group 1;\n")
#define CP_WAIT0()  asm volatile("cp.async.wait_group 0;\n")
#define LDSM4(R0, R1, R2, R3, A) asm volatile( \
    "ldmatrix.sync.aligned.m8n8.x4.shared.b16 {%0,%1,%2,%3}, [%4];" \
    : "=r"(R0), "=r"(R1), "=r"(R2), "=r"(R3) : "r"(A))

__device__ __forceinline__ void mma_bf16(float* c, const uint32_t* a, const uint32_t* b) {
    asm volatile(
        "mma.sync.aligned.m16n8k16.row.col.f32.bf16.bf16.f32 "
        "{%0,%1,%2,%3}, {%4,%5,%6,%7}, {%8,%9}, {%0,%1,%2,%3};\n"
        : "+f"(c[0]), "+f"(c[1]), "+f"(c[2]), "+f"(c[3])
        : "r"(a[0]), "r"(a[1]), "r"(a[2]), "r"(a[3]), "r"(b[0]), "r"(b[1]));
}
__device__ __forceinline__ float tanh_fast(float x) {
    float r;
    asm("tanh.approx.f32 %0, %1;" : "=f"(r) : "f"(x));
    return r;
}

// =====================================================================
// K0: prep+gates, one launch, 776 blocks.
//  [0,128):   hidden partials (W2b folded at kz==0)
//  [128,384): W1 transpose -> bf16
//  [384,768): GRU gate GEMM partials (2 paths x 8 kz x 24 c-tiles)
//  [768,776): zero g_ctx
// =====================================================================
__global__ void __launch_bounds__(256)
prep_gates_kernel(const float* __restrict__ s_t_m, const float* __restrict__ W2,
                  const float* __restrict__ W2b, const float* __restrict__ W1,
                  const float* __restrict__ h_t, const float* __restrict__ gWx,
                  const float* __restrict__ s0,  const float* __restrict__ gWh) {
    __shared__ float t[32][33];
    __shared__ float xs[64 * 8];
    __shared__ float Ws[8 * 64];
    const int bid = blockIdx.x, tid = threadIdx.x;

    if (bid >= 768) {
        int base = (bid - 768) * 4096 + tid * 16;
        float4 z = make_float4(0.f, 0.f, 0.f, 0.f);
        #pragma unroll
        for (int j = 0; j < 4; j++)
            *(float4*)(g_ctx + base + j * 4) = z;
        return;
    }

    if (bid < 128) {
        const int kz = bid >> 3, c0 = (bid & 7) * 64;
        const int tc = tid & 63, bh = tid >> 6;
        float acc[16];
        float binit = (kz == 0) ? W2b[c0 + tc] : 0.f;
        #pragma unroll
        for (int i = 0; i < 16; i++) acc[i] = binit;
        const int kbeg = kz * 32;
        for (int k0 = kbeg; k0 < kbeg + 32; k0 += 8) {
            #pragma unroll
            for (int j = 0; j < 2; j++) {
                int e = tid + j * 256;
                xs[e] = s_t_m[(e >> 3) * UNITS + k0 + (e & 7)];
            }
            #pragma unroll
            for (int j = 0; j < 2; j++) {
                int e = tid + j * 256;
                Ws[e] = W2[(size_t)(k0 + (e >> 6)) * UNITS + c0 + (e & 63)];
            }
            __syncthreads();
            #pragma unroll
            for (int kk = 0; kk < 8; kk++) {
                float wv = Ws[kk * 64 + tc];
                #pragma unroll
                for (int bb = 0; bb < 16; bb++)
                    acc[bb] += xs[(bh * 16 + bb) * 8 + kk] * wv;
            }
            __syncthreads();
        }
        #pragma unroll
        for (int bb = 0; bb < 16; bb++)
            g_hidP[((size_t)kz * BATCH + bh * 16 + bb) * UNITS + c0 + tc] = acc[bb];
    } else if (bid < 384) {
        const int tile = bid - 128;
        const int bx = (tile & 15) * 32, by = (tile >> 4) * 32;
        const int x = tid & 31, y0 = tid >> 5;
        #pragma unroll
        for (int dy = 0; dy < 32; dy += 8)
            t[y0 + dy][x] = W1[(size_t)(by + y0 + dy) * UNITS + bx + x];
        __syncthreads();
        #pragma unroll
        for (int dy = 0; dy < 32; dy += 8)
            g_W1Tb[(size_t)(bx + y0 + dy) * ENC + by + x] =
                __float2bfloat16(t[x][y0 + dy]);
    } else {
        const int gb = bid - 384;
        const int path = gb / 192, rem = gb % 192;
        const int kz = rem / 24, c0 = (rem % 24) * 64;
        const float* In = path ? s0 : h_t;
        const float* W  = path ? gWh : gWx;
        float* outP     = path ? g_ghP : g_gxP;
        const int tc = tid & 63, bh = tid >> 6;
        float acc[16];
        #pragma unroll
        for (int i = 0; i < 16; i++) acc[i] = 0.f;
        const int kbeg = kz * 64;
        for (int k0 = kbeg; k0 < kbeg + 64; k0 += 8) {
            #pragma unroll
            for (int j = 0; j < 2; j++) {
                int e = tid + j * 256;
                xs[e] = In[(e >> 3) * UNITS + k0 + (e & 7)];
            }
            #pragma unroll
            for (int j = 0; j < 2; j++) {
                int e = tid + j * 256;
                Ws[e] = W[(size_t)(k0 + (e >> 6)) * (3 * UNITS) + c0 + (e & 63)];
            }
            __syncthreads();
            #pragma unroll
            for (int kk = 0; kk < 8; kk++) {
                float wv = Ws[kk * 64 + tc];
                #pragma unroll
                for (int bb = 0; bb < 16; bb++)
                    acc[bb] += xs[(bh * 16 + bb) * 8 + kk] * wv;
            }
            __syncthreads();
        }
        #pragma unroll
        for (int bb = 0; bb < 16; bb++)
            outP[((size_t)kz * BATCH + bh * 16 + bb) * (3 * UNITS) + c0 + tc] = acc[bb];
    }
}

// =====================================================================
// K2: bf16 mma.sync + ldmatrix score GEMM, software-pipelined fragments
// (exact r12 best config: 256 threads, 2(M)x4(N) warps, warp tile 64x64).
// Block 128(T) x 256(N), K chunk 64; ny==0 blocks persist bf16 A to g_Hb.
// =====================================================================
#define SM_A(buf) ((uint32_t)(buf) * 16384u)
#define SM_B(buf) (32768u + (uint32_t)(buf) * 32768u)
#define SMEM_SCORE_BYTES 102400

__global__ void __launch_bounds__(256, 1)
score_kernel(const float* __restrict__ H, const float* __restrict__ W1b,
             const float* __restrict__ Vw) {
    extern __shared__ uint32_t dyn[];
    const int tid = threadIdx.x;
    const int bid = blockIdx.x;

    const int t0 = (bid & 15) * 128;
    const int ny = (bid >> 4) & 1;
    const int b  = bid >> 5;
    const int n0 = ny * 256;

    float* sbias = (float*)(dyn + 24576);
    float* sV    = sbias + 256;
    float* red   = sV + 256;

    const int w = tid >> 5, lane = tid & 31;
    const int g = lane >> 2, tig = lane & 3;
    const int warpM = w & 1, warpN = w >> 1;
    const uint32_t sbase = smem_u32(dyn);

    {
        float a = W1b[n0 + tid];
        #pragma unroll
        for (int p = 0; p < 16; p++)
            a += g_hidP[((size_t)p * BATCH + b) * UNITS + n0 + tid];
        sbias[tid] = a;
        sV[tid]    = Vw[n0 + tid];
    }

    const float* Af = H + ((size_t)b * TT + t0) * ENC;
    const __nv_bfloat16* Bg = g_W1Tb + (size_t)n0 * ENC;
    __nv_bfloat16* HbOut = g_Hb + ((size_t)b * TT + t0) * ENC;
    const bool writeHb = (ny == 0);

    float4 rA[8];
    auto ldgA = [&](int k0) {
        #pragma unroll
        for (int j = 0; j < 4; j++) {
            int i = tid + j * 256, r = i >> 3, sg = i & 7;
            const float4* src = (const float4*)(Af + (size_t)r * ENC + k0 + sg * 8);
            rA[j * 2]     = src[0];
            rA[j * 2 + 1] = src[1];
        }
    };
    auto stsA = [&](int buf, int k0) {
        #pragma unroll
        for (int j = 0; j < 4; j++) {
            int i = tid + j * 256, r = i >> 3, sg = i & 7;
            uint32_t off = SM_A(buf) + (uint32_t)r * 128u
                         + (uint32_t)((sg ^ (r & 7)) << 4);
            __nv_bfloat162 c0 = __floats2bfloat162_rn(rA[j*2].x,   rA[j*2].y);
            __nv_bfloat162 c1 = __floats2bfloat162_rn(rA[j*2].z,   rA[j*2].w);
            __nv_bfloat162 c2 = __floats2bfloat162_rn(rA[j*2+1].x, rA[j*2+1].y);
            __nv_bfloat162 c3 = __floats2bfloat162_rn(rA[j*2+1].z, rA[j*2+1].w);
            uint4 v;
            v.x = *(uint32_t*)&c0; v.y = *(uint32_t*)&c1;
            v.z = *(uint32_t*)&c2; v.w = *(uint32_t*)&c3;
            *(uint4*)((char*)dyn + off) = v;
            if (writeHb)
                *(uint4*)(HbOut + (size_t)r * ENC + k0 + sg * 8) = v;
        }
    };
    auto loadB = [&](int buf, int k0) {
        #pragma unroll
        for (int j = 0; j < 8; j++) {
            int e = tid + j * 256, r = e >> 3, s = e & 7;
            uint32_t off = SM_B(buf) + (uint32_t)r * 128u
                         + (uint32_t)((s ^ (r & 7)) << 4);
            CP16(sbase + off, Bg + (size_t)r * ENC + k0 + s * 8);
        }
    };

    uint32_t aOff[4], aRs[4], bOff[4], bRs[4];
    const uint32_t aHi = (lane >> 4) & 1;
    const uint32_t bHi = (lane >> 3) & 1;
    #pragma unroll
    for (int mt = 0; mt < 4; mt++) {
        int row = warpM * 64 + mt * 16 + (lane & 15);
        aOff[mt] = (uint32_t)row * 128u;
        aRs[mt]  = (uint32_t)(row & 7);
    }
    #pragma unroll
    for (int pr = 0; pr < 4; pr++) {
        int n = warpN * 64 + pr * 16 + (lane & 7) + ((lane >> 4) << 3);
        bOff[pr] = (uint32_t)n * 128u;
        bRs[pr]  = (uint32_t)(n & 7);
    }

    float acc[4][8][4];
    #pragma unroll
    for (int mt = 0; mt < 4; mt++)
        #pragma unroll
        for (int nt = 0; nt < 8; nt++)
            #pragma unroll
            for (int q = 0; q < 4; q++) acc[mt][nt][q] = 0.f;

    uint32_t afR[2][4], bqR[2][4][4];

    ldgA(0);
    loadB(0, 0);
    CP_COMMIT();
    stsA(0, 0);

    const int NS = ENC / 64;
    for (int s = 0; s < NS; s++) {
        if (s < NS - 1) {
            ldgA((s + 1) * 64);
            loadB((s + 1) & 1, (s + 1) * 64);
            CP_COMMIT();
            CP_WAIT1();
        } else {
            CP_WAIT0();
        }
        __syncthreads();
        const int cur = s & 1;

        #pragma unroll
        for (int pr = 0; pr < 4; pr++) {
            uint32_t addr = sbase + SM_B(cur) + bOff[pr]
                          + ((bHi ^ bRs[pr]) << 4);
            LDSM4(bqR[0][pr][0], bqR[0][pr][1], bqR[0][pr][2], bqR[0][pr][3], addr);
        }
        {
            uint32_t addr = sbase + SM_A(cur) + aOff[0] + ((aHi ^ aRs[0]) << 4);
            LDSM4(afR[0][0], afR[0][1], afR[0][2], afR[0][3], addr);
        }

        #pragma unroll
        for (int kk = 0; kk < 4; kk++) {
            const int bb = kk & 1;
            #pragma unroll
            for (int mt = 0; mt < 4; mt++) {
                if (mt < 3) {
                    uint32_t addr = sbase + SM_A(cur) + aOff[mt + 1]
                                  + (((((uint32_t)kk << 1) | aHi) ^ aRs[mt + 1]) << 4);
                    LDSM4(afR[(mt + 1) & 1][0], afR[(mt + 1) & 1][1],
                          afR[(mt + 1) & 1][2], afR[(mt + 1) & 1][3], addr);
                } else if (kk < 3) {
                    #pragma unroll
                    for (int pr = 0; pr < 4; pr++) {
                        uint32_t addr = sbase + SM_B(cur) + bOff[pr]
                                      + ((((((uint32_t)kk + 1) << 1) | bHi) ^ bRs[pr]) << 4);
                        LDSM4(bqR[bb ^ 1][pr][0], bqR[bb ^ 1][pr][1],
                              bqR[bb ^ 1][pr][2], bqR[bb ^ 1][pr][3], addr);
                    }
                    uint32_t addr = sbase + SM_A(cur) + aOff[0]
                                  + ((((((uint32_t)kk + 1) << 1) | aHi) ^ aRs[0]) << 4);
                    LDSM4(afR[0][0], afR[0][1], afR[0][2], afR[0][3], addr);
                }
                #pragma unroll
                for (int pr = 0; pr < 4; pr++) {
                    mma_bf16(acc[mt][pr * 2],     afR[mt & 1], &bqR[bb][pr][0]);
                    mma_bf16(acc[mt][pr * 2 + 1], afR[mt & 1], &bqR[bb][pr][2]);
                }
            }
        }
        if (s < NS - 1) stsA((s + 1) & 1, (s + 1) * 64);
    }

    float pa[4], pb[4];
    #pragma unroll
    for (int mt = 0; mt < 4; mt++) { pa[mt] = 0.f; pb[mt] = 0.f; }
    #pragma unroll
    for (int nt = 0; nt < 8; nt++) {
        int nn = warpN * 64 + nt * 8 + 2 * tig;
        float s0v = sbias[nn], s1v = sbias[nn + 1];
        float v0 = sV[nn],     v1 = sV[nn + 1];
        #pragma unroll
        for (int mt = 0; mt < 4; mt++) {
            pa[mt] += v0 * tanh_fast(acc[mt][nt][0] + s0v) + v1 * tanh_fast(acc[mt][nt][1] + s1v);
            pb[mt] += v0 * tanh_fast(acc[mt][nt][2] + s0v) + v1 * tanh_fast(acc[mt][nt][3] + s1v);
        }
    }
    #pragma unroll
    for (int mt = 0; mt < 4; mt++) {
        pa[mt] += __shfl_xor_sync(0xffffffffu, pa[mt], 1);
        pa[mt] += __shfl_xor_sync(0xffffffffu, pa[mt], 2);
        pb[mt] += __shfl_xor_sync(0xffffffffu, pb[mt], 1);
        pb[mt] += __shfl_xor_sync(0xffffffffu, pb[mt], 2);
    }
    if (tig == 0) {
        #pragma unroll
        for (int mt = 0; mt < 4; mt++) {
            int r = warpM * 64 + mt * 16 + g;
            red[warpN * 128 + r]     = pa[mt];
            red[warpN * 128 + r + 8] = pb[mt];
        }
    }
    __syncthreads();
    if (tid < 128) {
        float s = red[tid] + red[128 + tid] + red[256 + tid] + red[384 + tid];
        g_scoreP[((size_t)b * 2 + ny) * TT + t0 + tid] = s;
    }
}

// =====================================================================
// K3: context partials (fused softmax recompute) -> atomicAdd g_ctx,
//     + GRU combine + g_pc/g_fw init in extra column.
// grid (TCH+1, BATCH)
// =====================================================================
__global__ void __launch_bounds__(256)
context_kernel(const float* __restrict__ s0, const float* __restrict__ gbi,
               const float* __restrict__ gbr, const float* __restrict__ Wfab,
               const float* __restrict__ Wffb, const float* __restrict__ Wfhb,
               float* __restrict__ s_out) {
    int b = blockIdx.y, ch = blockIdx.x, tid = threadIdx.x;
    const int TC = TT / TCH;   // 128

    if (ch == TCH) {
        // GRU combine + g_pc/g_fw init
        for (int u = tid; u < UNITS; u += 256) {
            float xz = gbi[u], xr = gbi[UNITS + u], xh = gbi[2 * UNITS + u];
            float hz = gbr[u], hr = gbr[UNITS + u], hh = gbr[2 * UNITS + u];
            #pragma unroll
            for (int p = 0; p < 8; p++) {
                const float* X  = g_gxP + ((size_t)p * BATCH + b) * (3 * UNITS);
                const float* Hg = g_ghP + ((size_t)p * BATCH + b) * (3 * UNITS);
                xz += X[u];  xr += X[UNITS + u];  xh += X[2 * UNITS + u];
                hz += Hg[u]; hr += Hg[UNITS + u]; hh += Hg[2 * UNITS + u];
            }
            float hprev = s0[b * UNITS + u];
            float z  = 1.f / (1.f + expf(-(xz + hz)));
            float r  = 1.f / (1.f + expf(-(xr + hr)));
            float hc = tanhf(xh + r * hh);
            s_out[b * UNITS + u] = z * hprev + (1.f - z) * hc;
            g_pc[b * UNITS + u] = Wfab[u];
            g_fw[b * UNITS + u] = Wffb[u] + Wfhb[u];
        }
        return;
    }

    __shared__ float red[256];
    __shared__ float ws[TT / TCH];

    const float* s0p = g_scoreP + (size_t)b * 2 * TT;
    const float* s1p = s0p + TT;

    float sv[8];
    float mx = -1e30f;
    #pragma unroll
    for (int i = 0; i < 8; i++) {
        int t = tid + i * 256;
        sv[i] = s0p[t] + s1p[t];
        mx = fmaxf(mx, sv[i]);
    }
    red[tid] = mx; __syncthreads();
    for (int o = 128; o > 0; o >>= 1) {
        if (tid < o) red[tid] = fmaxf(red[tid], red[tid + o]);
        __syncthreads();
    }
    mx = red[0]; __syncthreads();
    float sum = 0.f;
    #pragma unroll
    for (int i = 0; i < 8; i++) sum += expf(sv[i] - mx);
    red[tid] = sum; __syncthreads();
    for (int o = 128; o > 0; o >>= 1) {
        if (tid < o) red[tid] += red[tid + o];
        __syncthreads();
    }
    float inv = 1.f / red[0];
    __syncthreads();

    int tBeg = ch * TC;
    if (tid < TC) {
        int t = tBeg + tid;
        ws[tid] = expf(s0p[t] + s1p[t] - mx) * inv;
    }
    __syncthreads();

    float ax = 0.f, ay = 0.f;
    const __nv_bfloat162* Hb =
        (const __nv_bfloat162*)(g_Hb + ((size_t)b * TT + tBeg) * ENC) + tid;
    #pragma unroll 8
    for (int t = 0; t < TC; t++) {
        float2 v = __bfloat1622float2(Hb[(size_t)t * (ENC / 2)]);
        ax += ws[t] * v.x;
        ay += ws[t] * v.y;
    }
    atomicAdd(g_ctx + (size_t)b * ENC + 2 * tid,     ax);
    atomicAdd(g_ctx + (size_t)b * ENC + 2 * tid + 1, ay);
}

// =====================================================================
// K4: pc partials = ctx @ Wfa -> atomicAdd g_pc. grid (8 ct, 16 kz).
// =====================================================================
__global__ void __launch_bounds__(256)
fusionB_kernel(const float* __restrict__ Wfa) {
    __shared__ float xs[64 * 8];
    __shared__ float Ws[8 * 64];
    const int c0 = blockIdx.x * 64;
    const int kz = blockIdx.y;
    const int tid = threadIdx.x, tc = tid & 63, bh = tid >> 6;
    float acc[16];
    #pragma unroll
    for (int i = 0; i < 16; i++) acc[i] = 0.f;
    const int kbeg = kz * 32;
    for (int k0 = kbeg; k0 < kbeg + 32; k0 += 8) {
        #pragma unroll
        for (int j = 0; j < 2; j++) {
            int e = tid + j * 256;
            xs[e] = g_ctx[(e >> 3) * ENC + k0 + (e & 7)];
        }
        #pragma unroll
        for (int j = 0; j < 2; j++) {
            int e = tid + j * 256;
            Ws[e] = Wfa[(size_t)(k0 + (e >> 6)) * UNITS + c0 + (e & 63)];
        }
        __syncthreads();
        #pragma unroll
        for (int kk = 0; kk < 8; kk++) {
            float wv = Ws[kk * 64 + tc];
            #pragma unroll
            for (int bb = 0; bb < 16; bb++)
                acc[bb] += xs[(bh * 16 + bb) * 8 + kk] * wv;
        }
        __syncthreads();
    }
    #pragma unroll
    for (int bb = 0; bb < 16; bb++)
        atomicAdd(g_pc + (size_t)(bh * 16 + bb) * UNITS + c0 + tc, acc[bb]);
}

// =====================================================================
// K5: fw partials: path0 = pc@Wff, path1 = st@Wfh -> atomicAdd g_fw.
// grid (8 ct, 16 kz, 2 path).
// =====================================================================
__global__ void __launch_bounds__(256)
fusionD_kernel(const float* __restrict__ Wff, const float* __restrict__ Wfh,
               const float* __restrict__ st) {
    __shared__ float xs[64 * 8];
    __shared__ float Ws[8 * 64];
    const int c0 = blockIdx.x * 64;
    const int kz = blockIdx.y;
    const int path = blockIdx.z;
    const float* W  = path ? Wfh : Wff;
    const float* In = path ? st  : g_pc;
    const int tid = threadIdx.x, tc = tid & 63, bh = tid >> 6;
    float acc[16];
    #pragma unroll
    for (int i = 0; i < 16; i++) acc[i] = 0.f;
    const int kbeg = kz * 32;
    for (int k0 = kbeg; k0 < kbeg + 32; k0 += 8) {
        #pragma unroll
        for (int j = 0; j < 2; j++) {
            int e = tid + j * 256;
            xs[e] = In[(e >> 3) * UNITS + k0 + (e & 7)];
        }
        #pragma unroll
        for (int j = 0; j < 2; j++) {
            int e = tid + j * 256;
            Ws[e] = W[(size_t)(k0 + (e >> 6)) * UNITS + c0 + (e & 63)];
        }
        __syncthreads();
        #pragma unroll
        for (int kk = 0; kk < 8; kk++) {
            float wv = Ws[kk * 64 + tc];
            #pragma unroll
            for (int bb = 0; bb < 16; bb++)
                acc[bb] += xs[(bh * 16 + bb) * 8 + kk] * wv;
        }
        __syncthreads();
    }
    #pragma unroll
    for (int bb = 0; bb < 16; bb++)
        atomicAdd(g_fw + (size_t)(bh * 16 + bb) * UNITS + c0 + tc, acc[bb]);
}

// =====================================================================
// K6: sigmoid + ft + vocab projection
// =====================================================================
__global__ void __launch_bounds__(512)
fusionE_kernel(const float* __restrict__ Wy, const float* __restrict__ Wyb,
               const float* __restrict__ st_in, float* __restrict__ y_out) {
    __shared__ float ft[UNITS], yred[512];
    int b = blockIdx.x, u = threadIdx.x;

    float fw = 1.f / (1.f + expf(-g_fw[b * UNITS + u]));
    float pc = g_pc[b * UNITS + u];
    float st = st_in[b * UNITS + u];
    ft[u] = pc * fw + st;
    __syncthreads();

    int v = u & 31, part = u >> 5;
    float acc = 0.f;
    for (int k = part; k < UNITS; k += 16) acc += ft[k] * Wy[(size_t)k * VOCAB + v];
    yred[u] = acc;
    __syncthreads();
    if (part == 0) {
        float s = Wyb[v];
        #pragma unroll
        for (int pp = 0; pp < 16; pp++) s += yred[pp * 32 + v];
        y_out[b * VOCAB + v] = s;
    }
}

// =====================================================================
extern "C" void kernel_launch(void* const* d_in, const int* in_sizes, int n_in,
                              void* d_out, int out_size) {
    const float* h_t   = (const float*)d_in[0];
    const float* s_t_m = (const float*)d_in[1];
    const float* H     = (const float*)d_in[2];
    const float* s0    = (const float*)d_in[3];
    const float* W1w   = (const float*)d_in[4];
    const float* W1b   = (const float*)d_in[5];
    const float* W2w   = (const float*)d_in[6];
    const float* W2b   = (const float*)d_in[7];
    const float* Vw    = (const float*)d_in[8];
    // d_in[9] = V_b: constant over t, cancels in softmax
    const float* gWx   = (const float*)d_in[10];
    const float* gWh   = (const float*)d_in[11];
    const float* gbi   = (const float*)d_in[12];
    const float* gbr   = (const float*)d_in[13];
    const float* Wfa   = (const float*)d_in[14];
    const float* Wfab  = (const float*)d_in[15];
    const float* Wff   = (const float*)d_in[16];
    const float* Wffb  = (const float*)d_in[17];
    const float* Wfh   = (const float*)d_in[18];
    const float* Wfhb  = (const float*)d_in[19];
    const float* Wy    = (const float*)d_in[20];
    const float* Wyb   = (const float*)d_in[21];

    float* out   = (float*)d_out;
    float* y_out = out;                       // y_t: [64, 32]
    float* s_out = out + BATCH * VOCAB;       // s_t: [64, 512]

    cudaFuncSetAttribute(score_kernel,
                         cudaFuncAttributeMaxDynamicSharedMemorySize, SMEM_SCORE_BYTES);

    prep_gates_kernel<<<776, 256>>>(s_t_m, W2w, W2b, W1w, h_t, gWx, s0, gWh);
    score_kernel<<<2048, 256, SMEM_SCORE_BYTES>>>(H, W1b, Vw);
    context_kernel<<<dim3(TCH + 1, BATCH), 256>>>(s0, gbi, gbr, Wfab, Wffb, Wfhb, s_out);
    fusionB_kernel<<<dim3(8, 16), 256>>>(Wfa);
    fusionD_kernel<<<dim3(8, 16, 2), 256>>>(Wff, Wfh, s_out);
    fusionE_kernel<<<BATCH, 512>>>(Wy, Wyb, s_out, y_out);
}

// round 16
// speedup vs baseline: 1.4378x; 1.4378x over previous
#include <cuda_runtime.h>
#include <cuda_bf16.h>
#include <math.h>
#include <stdint.h>

#define BATCH 64
#define TT    2048
#define ENC   512
#define UNITS 512
#define VOCAB 32
#define TCH   16

// ---- device scratch (no allocations allowed) ----
__device__ float g_scoreP[BATCH * 2 * TT];
__device__ float g_ctxP[BATCH * TCH * ENC];
__device__ float g_ctx[BATCH * ENC];
__device__ float g_gxP[8 * BATCH * 3 * UNITS];
__device__ float g_ghP[8 * BATCH * 3 * UNITS];
__device__ float g_hidP[16 * BATCH * UNITS];
__device__ float g_pcP[16 * BATCH * UNITS];
__device__ float g_pc[BATCH * UNITS];
__device__ float g_fwP[32 * BATCH * UNITS];
__device__ __align__(16) __nv_bfloat16 g_Hb[(size_t)BATCH * TT * ENC];  // bf16 H (written by score)
__device__ __align__(16) __nv_bfloat16 g_W1Tb[UNITS * ENC];             // W1^T bf16 [n][k]

// =====================================================================
// helpers
// =====================================================================
__device__ __forceinline__ uint32_t smem_u32(const void* p) {
    uint32_t a;
    asm("{ .reg .u64 t; cvta.to.shared.u64 t, %1; cvt.u32.u64 %0, t; }"
        : "=r"(a) : "l"(p));
    return a;
}
#define CP16(dst, src) asm volatile( \
    "cp.async.cg.shared.global [%0], [%1], 16;\n" :: "r"(dst), "l"(src))
#define CP_COMMIT() asm volatile("cp.async.commit_group;\n")
#define CP_WAIT1()  asm volatile("cp.async.wait_group 1;\n")
#define CP_WAIT0()  asm volatile("cp.async.wait_group 0;\n")
#define LDSM4(R0, R1, R2, R3, A) asm volatile( \
    "ldmatrix.sync.aligned.m8n8.x4.shared.b16 {%0,%1,%2,%3}, [%4];" \
    : "=r"(R0), "=r"(R1), "=r"(R2), "=r"(R3) : "r"(A))

__device__ __forceinline__ void mma_bf16(float* c, const uint32_t* a, const uint32_t* b) {
    asm volatile(
        "mma.sync.aligned.m16n8k16.row.col.f32.bf16.bf16.f32 "
        "{%0,%1,%2,%3}, {%4,%5,%6,%7}, {%8,%9}, {%0,%1,%2,%3};\n"
        : "+f"(c[0]), "+f"(c[1]), "+f"(c[2]), "+f"(c[3])
        : "r"(a[0]), "r"(a[1]), "r"(a[2]), "r"(a[3]), "r"(b[0]), "r"(b[1]));
}
__device__ __forceinline__ float tanh_fast(float x) {
    float r;
    asm("tanh.approx.f32 %0, %1;" : "=f"(r) : "f"(x));
    return r;
}

// =====================================================================
// K0: prep+gates, one launch, 768 blocks.
//  [0,128):   hidden partials (W2b folded at kz==0)
//  [128,384): W1 transpose -> bf16
//  [384,768): GRU gate GEMM partials (2 paths x 8 kz x 24 c-tiles)
// =====================================================================
__global__ void __launch_bounds__(256)
prep_gates_kernel(const float* __restrict__ s_t_m, const float* __restrict__ W2,
                  const float* __restrict__ W2b, const float* __restrict__ W1,
                  const float* __restrict__ h_t, const float* __restrict__ gWx,
                  const float* __restrict__ s0,  const float* __restrict__ gWh) {
    __shared__ float t[32][33];
    __shared__ float xs[64 * 8];
    __shared__ float Ws[8 * 64];
    const int bid = blockIdx.x, tid = threadIdx.x;

    if (bid < 128) {
        const int kz = bid >> 3, c0 = (bid & 7) * 64;
        const int tc = tid & 63, bh = tid >> 6;
        float acc[16];
        float binit = (kz == 0) ? W2b[c0 + tc] : 0.f;
        #pragma unroll
        for (int i = 0; i < 16; i++) acc[i] = binit;
        const int kbeg = kz * 32;
        for (int k0 = kbeg; k0 < kbeg + 32; k0 += 8) {
            #pragma unroll
            for (int j = 0; j < 2; j++) {
                int e = tid + j * 256;
                xs[e] = s_t_m[(e >> 3) * UNITS + k0 + (e & 7)];
            }
            #pragma unroll
            for (int j = 0; j < 2; j++) {
                int e = tid + j * 256;
                Ws[e] = W2[(size_t)(k0 + (e >> 6)) * UNITS + c0 + (e & 63)];
            }
            __syncthreads();
            #pragma unroll
            for (int kk = 0; kk < 8; kk++) {
                float wv = Ws[kk * 64 + tc];
                #pragma unroll
                for (int bb = 0; bb < 16; bb++)
                    acc[bb] += xs[(bh * 16 + bb) * 8 + kk] * wv;
            }
            __syncthreads();
        }
        #pragma unroll
        for (int bb = 0; bb < 16; bb++)
            g_hidP[((size_t)kz * BATCH + bh * 16 + bb) * UNITS + c0 + tc] = acc[bb];
    } else if (bid < 384) {
        const int tile = bid - 128;
        const int bx = (tile & 15) * 32, by = (tile >> 4) * 32;
        const int x = tid & 31, y0 = tid >> 5;
        #pragma unroll
        for (int dy = 0; dy < 32; dy += 8)
            t[y0 + dy][x] = W1[(size_t)(by + y0 + dy) * UNITS + bx + x];
        __syncthreads();
        #pragma unroll
        for (int dy = 0; dy < 32; dy += 8)
            g_W1Tb[(size_t)(bx + y0 + dy) * ENC + by + x] =
                __float2bfloat16(t[x][y0 + dy]);
    } else {
        const int gb = bid - 384;
        const int path = gb / 192, rem = gb % 192;
        const int kz = rem / 24, c0 = (rem % 24) * 64;
        const float* In = path ? s0 : h_t;
        const float* W  = path ? gWh : gWx;
        float* outP     = path ? g_ghP : g_gxP;
        const int tc = tid & 63, bh = tid >> 6;
        float acc[16];
        #pragma unroll
        for (int i = 0; i < 16; i++) acc[i] = 0.f;
        const int kbeg = kz * 64;
        for (int k0 = kbeg; k0 < kbeg + 64; k0 += 8) {
            #pragma unroll
            for (int j = 0; j < 2; j++) {
                int e = tid + j * 256;
                xs[e] = In[(e >> 3) * UNITS + k0 + (e & 7)];
            }
            #pragma unroll
            for (int j = 0; j < 2; j++) {
                int e = tid + j * 256;
                Ws[e] = W[(size_t)(k0 + (e >> 6)) * (3 * UNITS) + c0 + (e & 63)];
            }
            __syncthreads();
            #pragma unroll
            for (int kk = 0; kk < 8; kk++) {
                float wv = Ws[kk * 64 + tc];
                #pragma unroll
                for (int bb = 0; bb < 16; bb++)
                    acc[bb] += xs[(bh * 16 + bb) * 8 + kk] * wv;
            }
            __syncthreads();
        }
        #pragma unroll
        for (int bb = 0; bb < 16; bb++)
            outP[((size_t)kz * BATCH + bh * 16 + bb) * (3 * UNITS) + c0 + tc] = acc[bb];
    }
}

// =====================================================================
// K2: bf16 mma.sync + ldmatrix score GEMM, software-pipelined fragments.
// Block 128(T) x 256(N), K chunk 64; ny==0 blocks persist bf16 A to g_Hb.
// =====================================================================
#define SM_A(buf) ((uint32_t)(buf) * 16384u)
#define SM_B(buf) (32768u + (uint32_t)(buf) * 32768u)
#define SMEM_SCORE_BYTES 102400

__global__ void __launch_bounds__(256, 1)
score_kernel(const float* __restrict__ H, const float* __restrict__ W1b,
             const float* __restrict__ Vw) {
    extern __shared__ uint32_t dyn[];
    const int tid = threadIdx.x;
    const int bid = blockIdx.x;

    const int t0 = (bid & 15) * 128;
    const int ny = (bid >> 4) & 1;
    const int b  = bid >> 5;
    const int n0 = ny * 256;

    float* sbias = (float*)(dyn + 24576);
    float* sV    = sbias + 256;
    float* red   = sV + 256;

    const int w = tid >> 5, lane = tid & 31;
    const int g = lane >> 2, tig = lane & 3;
    const int warpM = w & 1, warpN = w >> 1;
    const uint32_t sbase = smem_u32(dyn);

    {
        float a = W1b[n0 + tid];
        #pragma unroll
        for (int p = 0; p < 16; p++)
            a += g_hidP[((size_t)p * BATCH + b) * UNITS + n0 + tid];
        sbias[tid] = a;
        sV[tid]    = Vw[n0 + tid];
    }

    const float* Af = H + ((size_t)b * TT + t0) * ENC;
    const __nv_bfloat16* Bg = g_W1Tb + (size_t)n0 * ENC;
    __nv_bfloat16* HbOut = g_Hb + ((size_t)b * TT + t0) * ENC;
    const bool writeHb = (ny == 0);

    float4 rA[8];
    auto ldgA = [&](int k0) {
        #pragma unroll
        for (int j = 0; j < 4; j++) {
            int i = tid + j * 256, r = i >> 3, sg = i & 7;
            const float4* src = (const float4*)(Af + (size_t)r * ENC + k0 + sg * 8);
            rA[j * 2]     = src[0];
            rA[j * 2 + 1] = src[1];
        }
    };
    auto stsA = [&](int buf, int k0) {
        #pragma unroll
        for (int j = 0; j < 4; j++) {
            int i = tid + j * 256, r = i >> 3, sg = i & 7;
            uint32_t off = SM_A(buf) + (uint32_t)r * 128u
                         + (uint32_t)((sg ^ (r & 7)) << 4);
            __nv_bfloat162 c0 = __floats2bfloat162_rn(rA[j*2].x,   rA[j*2].y);
            __nv_bfloat162 c1 = __floats2bfloat162_rn(rA[j*2].z,   rA[j*2].w);
            __nv_bfloat162 c2 = __floats2bfloat162_rn(rA[j*2+1].x, rA[j*2+1].y);
            __nv_bfloat162 c3 = __floats2bfloat162_rn(rA[j*2+1].z, rA[j*2+1].w);
            uint4 v;
            v.x = *(uint32_t*)&c0; v.y = *(uint32_t*)&c1;
            v.z = *(uint32_t*)&c2; v.w = *(uint32_t*)&c3;
            *(uint4*)((char*)dyn + off) = v;
            if (writeHb)
                *(uint4*)(HbOut + (size_t)r * ENC + k0 + sg * 8) = v;
        }
    };
    auto loadB = [&](int buf, int k0) {
        #pragma unroll
        for (int j = 0; j < 8; j++) {
            int e = tid + j * 256, r = e >> 3, s = e & 7;
            uint32_t off = SM_B(buf) + (uint32_t)r * 128u
                         + (uint32_t)((s ^ (r & 7)) << 4);
            CP16(sbase + off, Bg + (size_t)r * ENC + k0 + s * 8);
        }
    };

    uint32_t aOff[4], aRs[4], bOff[4], bRs[4];
    const uint32_t aHi = (lane >> 4) & 1;
    const uint32_t bHi = (lane >> 3) & 1;
    #pragma unroll
    for (int mt = 0; mt < 4; mt++) {
        int row = warpM * 64 + mt * 16 + (lane & 15);
        aOff[mt] = (uint32_t)row * 128u;
        aRs[mt]  = (uint32_t)(row & 7);
    }
    #pragma unroll
    for (int pr = 0; pr < 4; pr++) {
        int n = warpN * 64 + pr * 16 + (lane & 7) + ((lane >> 4) << 3);
        bOff[pr] = (uint32_t)n * 128u;
        bRs[pr]  = (uint32_t)(n & 7);
    }

    float acc[4][8][4];
    #pragma unroll
    for (int mt = 0; mt < 4; mt++)
        #pragma unroll
        for (int nt = 0; nt < 8; nt++)
            #pragma unroll
            for (int q = 0; q < 4; q++) acc[mt][nt][q] = 0.f;

    uint32_t afR[2][4], bqR[2][4][4];

    ldgA(0);
    loadB(0, 0);
    CP_COMMIT();
    stsA(0, 0);

    const int NS = ENC / 64;
    for (int s = 0; s < NS; s++) {
        if (s < NS - 1) {
            ldgA((s + 1) * 64);
            loadB((s + 1) & 1, (s + 1) * 64);
            CP_COMMIT();
            CP_WAIT1();
        } else {
            CP_WAIT0();
        }
        __syncthreads();
        const int cur = s & 1;

        #pragma unroll
        for (int pr = 0; pr < 4; pr++) {
            uint32_t addr = sbase + SM_B(cur) + bOff[pr]
                          + ((bHi ^ bRs[pr]) << 4);
            LDSM4(bqR[0][pr][0], bqR[0][pr][1], bqR[0][pr][2], bqR[0][pr][3], addr);
        }
        {
            uint32_t addr = sbase + SM_A(cur) + aOff[0] + ((aHi ^ aRs[0]) << 4);
            LDSM4(afR[0][0], afR[0][1], afR[0][2], afR[0][3], addr);
        }

        #pragma unroll
        for (int kk = 0; kk < 4; kk++) {
            const int bb = kk & 1;
            #pragma unroll
            for (int mt = 0; mt < 4; mt++) {
                if (mt < 3) {
                    uint32_t addr = sbase + SM_A(cur) + aOff[mt + 1]
                                  + (((((uint32_t)kk << 1) | aHi) ^ aRs[mt + 1]) << 4);
                    LDSM4(afR[(mt + 1) & 1][0], afR[(mt + 1) & 1][1],
                          afR[(mt + 1) & 1][2], afR[(mt + 1) & 1][3], addr);
                } else if (kk < 3) {
                    #pragma unroll
                    for (int pr = 0; pr < 4; pr++) {
                        uint32_t addr = sbase + SM_B(cur) + bOff[pr]
                                      + ((((((uint32_t)kk + 1) << 1) | bHi) ^ bRs[pr]) << 4);
                        LDSM4(bqR[bb ^ 1][pr][0], bqR[bb ^ 1][pr][1],
                              bqR[bb ^ 1][pr][2], bqR[bb ^ 1][pr][3], addr);
                    }
                    uint32_t addr = sbase + SM_A(cur) + aOff[0]
                                  + ((((((uint32_t)kk + 1) << 1) | aHi) ^ aRs[0]) << 4);
                    LDSM4(afR[0][0], afR[0][1], afR[0][2], afR[0][3], addr);
                }
                #pragma unroll
                for (int pr = 0; pr < 4; pr++) {
                    mma_bf16(acc[mt][pr * 2],     afR[mt & 1], &bqR[bb][pr][0]);
                    mma_bf16(acc[mt][pr * 2 + 1], afR[mt & 1], &bqR[bb][pr][2]);
                }
            }
        }
        if (s < NS - 1) stsA((s + 1) & 1, (s + 1) * 64);
    }

    float pa[4], pb[4];
    #pragma unroll
    for (int mt = 0; mt < 4; mt++) { pa[mt] = 0.f; pb[mt] = 0.f; }
    #pragma unroll
    for (int nt = 0; nt < 8; nt++) {
        int nn = warpN * 64 + nt * 8 + 2 * tig;
        float s0v = sbias[nn], s1v = sbias[nn + 1];
        float v0 = sV[nn],     v1 = sV[nn + 1];
        #pragma unroll
        for (int mt = 0; mt < 4; mt++) {
            pa[mt] += v0 * tanh_fast(acc[mt][nt][0] + s0v) + v1 * tanh_fast(acc[mt][nt][1] + s1v);
            pb[mt] += v0 * tanh_fast(acc[mt][nt][2] + s0v) + v1 * tanh_fast(acc[mt][nt][3] + s1v);
        }
    }
    #pragma unroll
    for (int mt = 0; mt < 4; mt++) {
        pa[mt] += __shfl_xor_sync(0xffffffffu, pa[mt], 1);
        pa[mt] += __shfl_xor_sync(0xffffffffu, pa[mt], 2);
        pb[mt] += __shfl_xor_sync(0xffffffffu, pb[mt], 1);
        pb[mt] += __shfl_xor_sync(0xffffffffu, pb[mt], 2);
    }
    if (tig == 0) {
        #pragma unroll
        for (int mt = 0; mt < 4; mt++) {
            int r = warpM * 64 + mt * 16 + g;
            red[warpN * 128 + r]     = pa[mt];
            red[warpN * 128 + r + 8] = pb[mt];
        }
    }
    __syncthreads();
    if (tid < 128) {
        float s = red[tid] + red[128 + tid] + red[256 + tid] + red[384 + tid];
        g_scoreP[((size_t)b * 2 + ny) * TT + t0 + tid] = s;
    }
}

// =====================================================================
// K3: context partials (fused softmax recompute) + GRU combine.
// grid (TCH+1, BATCH): x<TCH -> context chunk; x==TCH -> GRU combine.
// =====================================================================
__global__ void __launch_bounds__(256)
context_kernel(const float* __restrict__ s0, const float* __restrict__ gbi,
               const float* __restrict__ gbr, float* __restrict__ s_out) {
    int b = blockIdx.y, ch = blockIdx.x, tid = threadIdx.x;
    const int TC = TT / TCH;   // 128

    if (ch == TCH) {
        for (int u = tid; u < UNITS; u += 256) {
            float xz = gbi[u], xr = gbi[UNITS + u], xh = gbi[2 * UNITS + u];
            float hz = gbr[u], hr = gbr[UNITS + u], hh = gbr[2 * UNITS + u];
            #pragma unroll
            for (int p = 0; p < 8; p++) {
                const float* X  = g_gxP + ((size_t)p * BATCH + b) * (3 * UNITS);
                const float* Hg = g_ghP + ((size_t)p * BATCH + b) * (3 * UNITS);
                xz += X[u];  xr += X[UNITS + u];  xh += X[2 * UNITS + u];
                hz += Hg[u]; hr += Hg[UNITS + u]; hh += Hg[2 * UNITS + u];
            }
            float hprev = s0[b * UNITS + u];
            float z  = 1.f / (1.f + expf(-(xz + hz)));
            float r  = 1.f / (1.f + expf(-(xr + hr)));
            float hc = tanhf(xh + r * hh);
            s_out[b * UNITS + u] = z * hprev + (1.f - z) * hc;
        }
        return;
    }

    __shared__ float red[256];
    __shared__ float ws[TT / TCH];

    const float* s0p = g_scoreP + (size_t)b * 2 * TT;
    const float* s1p = s0p + TT;

    float sv[8];
    float mx = -1e30f;
    #pragma unroll
    for (int i = 0; i < 8; i++) {
        int t = tid + i * 256;
        sv[i] = s0p[t] + s1p[t];
        mx = fmaxf(mx, sv[i]);
    }
    red[tid] = mx; __syncthreads();
    for (int o = 128; o > 0; o >>= 1) {
        if (tid < o) red[tid] = fmaxf(red[tid], red[tid + o]);
        __syncthreads();
    }
    mx = red[0]; __syncthreads();
    float sum = 0.f;
    #pragma unroll
    for (int i = 0; i < 8; i++) sum += expf(sv[i] - mx);
    red[tid] = sum; __syncthreads();
    for (int o = 128; o > 0; o >>= 1) {
        if (tid < o) red[tid] += red[tid + o];
        __syncthreads();
    }
    float inv = 1.f / red[0];
    __syncthreads();

    int tBeg = ch * TC;
    if (tid < TC) {
        int t = tBeg + tid;
        ws[tid] = expf(s0p[t] + s1p[t] - mx) * inv;
    }
    __syncthreads();

    float ax = 0.f, ay = 0.f;
    const __nv_bfloat162* Hb =
        (const __nv_bfloat162*)(g_Hb + ((size_t)b * TT + tBeg) * ENC) + tid;
    #pragma unroll 8
    for (int t = 0; t < TC; t++) {
        float2 v = __bfloat1622float2(Hb[(size_t)t * (ENC / 2)]);
        ax += ws[t] * v.x;
        ay += ws[t] * v.y;
    }
    float* dst = g_ctxP + ((size_t)b * TCH + ch) * ENC + 2 * tid;
    dst[0] = ax; dst[1] = ay;
}

// =====================================================================
// K3b: ctx combine
// =====================================================================
__global__ void __launch_bounds__(512)
ctx_combine_kernel() {
    int b = blockIdx.x, e = threadIdx.x;
    float v = 0.f;
    #pragma unroll
    for (int p = 0; p < TCH; p++)
        v += g_ctxP[((size_t)b * TCH + p) * ENC + e];
    g_ctx[b * ENC + e] = v;
}

// =====================================================================
// K4: pc partials = ctx @ Wfa.  grid (8 ct of 64, 16 kz of 32).
// =====================================================================
__global__ void __launch_bounds__(256)
fusionB_kernel(const float* __restrict__ Wfa) {
    __shared__ float xs[64 * 8];
    __shared__ float Ws[8 * 64];
    const int c0 = blockIdx.x * 64;
    const int kz = blockIdx.y;
    const int tid = threadIdx.x, tc = tid & 63, bh = tid >> 6;
    float acc[16];
    #pragma unroll
    for (int i = 0; i < 16; i++) acc[i] = 0.f;
    const int kbeg = kz * 32;
    for (int k0 = kbeg; k0 < kbeg + 32; k0 += 8) {
        #pragma unroll
        for (int j = 0; j < 2; j++) {
            int e = tid + j * 256;
            xs[e] = g_ctx[(e >> 3) * ENC + k0 + (e & 7)];
        }
        #pragma unroll
        for (int j = 0; j < 2; j++) {
            int e = tid + j * 256;
            Ws[e] = Wfa[(size_t)(k0 + (e >> 6)) * UNITS + c0 + (e & 63)];
        }
        __syncthreads();
        #pragma unroll
        for (int kk = 0; kk < 8; kk++) {
            float wv = Ws[kk * 64 + tc];
            #pragma unroll
            for (int bb = 0; bb < 16; bb++)
                acc[bb] += xs[(bh * 16 + bb) * 8 + kk] * wv;
        }
        __syncthreads();
    }
    #pragma unroll
    for (int bb = 0; bb < 16; bb++)
        g_pcP[((size_t)kz * BATCH + bh * 16 + bb) * UNITS + c0 + tc] = acc[bb];
}

// =====================================================================
// K4b: pc combine
// =====================================================================
__global__ void __launch_bounds__(512)
pc_combine_kernel(const float* __restrict__ Wfab) {
    int b = blockIdx.x, u = threadIdx.x;
    float v = Wfab[u];
    #pragma unroll
    for (int p = 0; p < 16; p++)
        v += g_pcP[((size_t)p * BATCH + b) * UNITS + u];
    g_pc[b * UNITS + u] = v;
}

// =====================================================================
// K5: fw partials: path0 = pc@Wff, path1 = st@Wfh. (8 ct, 16 kz, 2)
// =====================================================================
__global__ void __launch_bounds__(256)
fusionD_kernel(const float* __restrict__ Wff, const float* __restrict__ Wfh,
               const float* __restrict__ st) {
    __shared__ float xs[64 * 8];
    __shared__ float Ws[8 * 64];
    const int c0 = blockIdx.x * 64;
    const int kz = blockIdx.y;
    const int path = blockIdx.z;
    const float* W  = path ? Wfh : Wff;
    const float* In = path ? st  : g_pc;
    const int tid = threadIdx.x, tc = tid & 63, bh = tid >> 6;
    float acc[16];
    #pragma unroll
    for (int i = 0; i < 16; i++) acc[i] = 0.f;
    const int kbeg = kz * 32;
    for (int k0 = kbeg; k0 < kbeg + 32; k0 += 8) {
        #pragma unroll
        for (int j = 0; j < 2; j++) {
            int e = tid + j * 256;
            xs[e] = In[(e >> 3) * UNITS + k0 + (e & 7)];
        }
        #pragma unroll
        for (int j = 0; j < 2; j++) {
            int e = tid + j * 256;
            Ws[e] = W[(size_t)(k0 + (e >> 6)) * UNITS + c0 + (e & 63)];
        }
        __syncthreads();
        #pragma unroll
        for (int kk = 0; kk < 8; kk++) {
            float wv = Ws[kk * 64 + tc];
            #pragma unroll
            for (int bb = 0; bb < 16; bb++)
                acc[bb] += xs[(bh * 16 + bb) * 8 + kk] * wv;
        }
        __syncthreads();
    }
    #pragma unroll
    for (int bb = 0; bb < 16; bb++)
        g_fwP[((size_t)(path * 16 + kz) * BATCH + bh * 16 + bb) * UNITS + c0 + tc] = acc[bb];
}

// =====================================================================
// K6: fw combine + sigmoid + ft + vocab projection
// =====================================================================
__global__ void __launch_bounds__(512)
fusionE_kernel(const float* __restrict__ Wffb, const float* __restrict__ Wfhb,
               const float* __restrict__ Wy,   const float* __restrict__ Wyb,
               const float* __restrict__ st_in, float* __restrict__ y_out) {
    __shared__ float ft[UNITS], yred[512];
    int b = blockIdx.x, u = threadIdx.x;

    float fw = Wffb[u] + Wfhb[u];
    #pragma unroll
    for (int p = 0; p < 32; p++)
        fw += g_fwP[((size_t)p * BATCH + b) * UNITS + u];
    fw = 1.f / (1.f + expf(-fw));

    float pc = g_pc[b * UNITS + u];
    float st = st_in[b * UNITS + u];
    ft[u] = pc * fw + st;
    __syncthreads();

    int v = u & 31, part = u >> 5;
    float acc = 0.f;
    for (int k = part; k < UNITS; k += 16) acc += ft[k] * Wy[(size_t)k * VOCAB + v];
    yred[u] = acc;
    __syncthreads();
    if (part == 0) {
        float s = Wyb[v];
        #pragma unroll
        for (int pp = 0; pp < 16; pp++) s += yred[pp * 32 + v];
        y_out[b * VOCAB + v] = s;
    }
}

// =====================================================================
extern "C" void kernel_launch(void* const* d_in, const int* in_sizes, int n_in,
                              void* d_out, int out_size) {
    const float* h_t   = (const float*)d_in[0];
    const float* s_t_m = (const float*)d_in[1];
    const float* H     = (const float*)d_in[2];
    const float* s0    = (const float*)d_in[3];
    const float* W1w   = (const float*)d_in[4];
    const float* W1b   = (const float*)d_in[5];
    const float* W2w   = (const float*)d_in[6];
    const float* W2b   = (const float*)d_in[7];
    const float* Vw    = (const float*)d_in[8];
    // d_in[9] = V_b: constant over t, cancels in softmax
    const float* gWx   = (const float*)d_in[10];
    const float* gWh   = (const float*)d_in[11];
    const float* gbi   = (const float*)d_in[12];
    const float* gbr   = (const float*)d_in[13];
    const float* Wfa   = (const float*)d_in[14];
    const float* Wfab  = (const float*)d_in[15];
    const float* Wff   = (const float*)d_in[16];
    const float* Wffb  = (const float*)d_in[17];
    const float* Wfh   = (const float*)d_in[18];
    const float* Wfhb  = (const float*)d_in[19];
    const float* Wy    = (const float*)d_in[20];
    const float* Wyb   = (const float*)d_in[21];

    float* out   = (float*)d_out;
    float* y_out = out;                       // y_t: [64, 32]
    float* s_out = out + BATCH * VOCAB;       // s_t: [64, 512]

    cudaFuncSetAttribute(score_kernel,
                         cudaFuncAttributeMaxDynamicSharedMemorySize, SMEM_SCORE_BYTES);

    prep_gates_kernel<<<768, 256>>>(s_t_m, W2w, W2b, W1w, h_t, gWx, s0, gWh);
    score_kernel<<<2048, 256, SMEM_SCORE_BYTES>>>(H, W1b, Vw);
    context_kernel<<<dim3(TCH + 1, BATCH), 256>>>(s0, gbi, gbr, s_out);
    ctx_combine_kernel<<<BATCH, 512>>>();
    fusionB_kernel<<<dim3(8, 16), 256>>>(Wfa);
    pc_combine_kernel<<<BATCH, 512>>>(Wfab);
    fusionD_kernel<<<dim3(8, 16, 2), 256>>>(Wff, Wfh, s_out);
    fusionE_kernel<<<BATCH, 512>>>(Wffb, Wfhb, Wy, Wyb, s_out, y_out);
}